// round 15
// baseline (speedup 1.0000x reference)
#include <cuda_runtime.h>
#include <cstdint>

// Loss_60567628808292: YOLO loss (bugs faithfully reproduced), fully fused.
// pred, target: [batch, 7, 7, 30] float32; M = batch*49 rows of 30 floats.
// out: scalar float32 = bbox_loss + noobj_loss.
//
// R13 design with a DEEPER per-CTA pipeline: 1 CTA/SM (grid 152), 8-stage
// TMA ring x 23 KB = 184 KB smem/CTA -> 16 outstanding bulk copies per SM
// (2x R13). L2 pinning: 64 MB pred + 24 MB tgt prefixes evict_last; rest
// evict_first. Warm-replay limiter hypothesis: per-SM TMA chain depth.

#define NCH 30
#define SDIM 7.0f
#define L_COORD 5.0f
#define L_NOOBJ 0.5f
#define MAX_ACTIVE 49   /* S*S */
#define THREADS 256

#define TILE_ROWS 96
#define TILE_BYTES (TILE_ROWS * NCH * 4)   /* 11520 B per tensor    */
#define STAGE_BYTES (2 * TILE_BYTES)       /* 23040 B (pred+tgt)    */
#define NSTAGES 8
#define DYN_SMEM (NSTAGES * STAGE_BYTES)   /* 184320 B              */
#define NOOBJ_BLOCKS 151                   /* +1 bbox = 152 = 1/SM  */

#define SPLIT_PRED (64ull * 1024 * 1024)   /* pred prefix kept in L2 */
#define SPLIT_TGT  (24ull * 1024 * 1024)   /* tgt  prefix kept in L2 */

// Cross-block accumulator + completion counter. Zero at load; last block
// publishes out[] and resets both -> same initial state every graph replay.
__device__ float g_acc;
__device__ unsigned int g_done;

// ---------------------------------------------------------------------------
static __device__ __forceinline__ uint32_t smem_u32(const void* p) {
    uint32_t a;
    asm("{ .reg .u64 t; cvta.to.shared.u64 t, %1; cvt.u32.u64 %0, t; }"
        : "=r"(a) : "l"(p));
    return a;
}

static __device__ __forceinline__ void mbar_init(uint32_t mbar, uint32_t cnt) {
    asm volatile("mbarrier.init.shared.b64 [%0], %1;" :: "r"(mbar), "r"(cnt) : "memory");
}

static __device__ __forceinline__ void mbar_expect_tx(uint32_t mbar, uint32_t bytes) {
    asm volatile("mbarrier.arrive.expect_tx.shared.b64 _, [%0], %1;"
                 :: "r"(mbar), "r"(bytes) : "memory");
}

static __device__ __forceinline__ uint64_t policy_evict_last() {
    uint64_t p;
    asm("createpolicy.fractional.L2::evict_last.b64 %0, 1.0;" : "=l"(p));
    return p;
}

static __device__ __forceinline__ uint64_t policy_evict_first() {
    uint64_t p;
    asm("createpolicy.fractional.L2::evict_first.b64 %0, 1.0;" : "=l"(p));
    return p;
}

static __device__ __forceinline__ void bulk_g2s_pol(uint32_t dst, const void* src,
                                                    uint32_t bytes, uint32_t mbar,
                                                    uint64_t pol) {
    asm volatile(
        "cp.async.bulk.shared::cluster.global.mbarrier::complete_tx::bytes"
        ".L2::cache_hint [%0], [%1], %2, [%3], %4;"
        :: "r"(dst), "l"(src), "r"(bytes), "r"(mbar), "l"(pol) : "memory");
}

static __device__ __forceinline__ void mbar_wait(uint32_t mbar, uint32_t parity) {
    asm volatile(
        "{\n\t"
        ".reg .pred P;\n\t"
        "WAIT_%=:\n\t"
        "mbarrier.try_wait.parity.acquire.cta.shared::cta.b64 P, [%0], %1, 0x989680;\n\t"
        "@P bra DONE_%=;\n\t"
        "bra WAIT_%=;\n\t"
        "DONE_%=:\n\t"
        "}"
        :: "r"(mbar), "r"(parity) : "memory");
}

// ---------------------------------------------------------------------------
// Per-box "tot" value (l1+l2+l3+iou), reproducing the reference's buggy
// transform: x1 = x/7 - w/2 ; x2 = x1/7 + w/2 (uses the NEW xy).
// ---------------------------------------------------------------------------
__device__ __forceinline__ float box_tot(const float* __restrict__ pb,
                                         const float* __restrict__ tb,
                                         float& iou) {
    const float inv7 = 1.0f / SDIM;

    const float px = pb[0], py = pb[1], pw = pb[2], ph = pb[3], pc = pb[4];
    const float tx = tb[0], ty = tb[1], tw = tb[2], th = tb[3], tc = tb[4];

    const float px1 = px * inv7 - 0.5f * pw;
    const float py1 = py * inv7 - 0.5f * ph;
    const float px2 = px1 * inv7 + 0.5f * pw;   // original bug
    const float py2 = py1 * inv7 + 0.5f * ph;

    const float tx1 = tx * inv7 - 0.5f * tw;
    const float ty1 = ty * inv7 - 0.5f * th;
    const float tx2 = tx1 * inv7 + 0.5f * tw;
    const float ty2 = ty1 * inv7 + 0.5f * th;

    const float dx1 = tx1 - px1, dy1 = ty1 - py1;
    const float l1 = L_COORD * dx1 * dx1 + dy1 * dy1;   // lambda only on x (bug)

    const float sx = sqrtf(tx2) - sqrtf(px2);
    const float sy = sqrtf(ty2) - sqrtf(py2);
    const float l2 = L_COORD * sx * sx + sy * sy;       // lambda only on x (bug)

    const float dc = tc - pc;
    const float l3 = dc * dc;

    const float ltx = fmaxf(px1, tx1), lty = fmaxf(py1, ty1);
    const float rbx = fminf(px2, tx2), rby = fminf(py2, ty2);
    const float wx = fmaxf(rbx - ltx, 0.0f);
    const float wy = fmaxf(rby - lty, 0.0f);
    const float inter = wx * wy;
    const float ap = (px2 - px1) * (py2 - py1);
    const float at = (tx2 - tx1) * (ty2 - ty1);
    iou = inter / (ap + at - inter);

    return l1 + l2 + l3 + iou;   // IoU added into the selected loss (bug)
}

// ---------------------------------------------------------------------------
// Fused kernel.
//   block 0        : bbox loss (first MAX_ACTIVE obj rows in flatten order)
//   blocks >= 1    : noobj loss, 8-stage TMA ring over 96-row tiles.
// ---------------------------------------------------------------------------
__global__ void __launch_bounds__(THREADS)
yolo_loss_kernel(const float* __restrict__ pred,
                 const float* __restrict__ tgt,
                 int M, float* __restrict__ out) {
    extern __shared__ __align__(128) float dyn[];   // NSTAGES x [pred | tgt]
    __shared__ uint64_t mbar_store[NSTAGES];

    const int tid = threadIdx.x;
    const int lane = tid & 31;
    const int w = tid >> 5;
    float partial = 0.0f;   // valid on tid==0 at the end

    if (blockIdx.x == 0) {
        // ---------------- bbox scan ----------------
        __shared__ float s_acc;
        __shared__ int s_count;
        __shared__ int s_warp_cnt[THREADS / 32];
        const int nwarps = THREADS / 32;

        if (tid == 0) { s_acc = 0.0f; s_count = 0; }
        __syncthreads();

        for (int base = 0; base < M; base += THREADS) {
            const int r = base + tid;
            bool obj = false;
            if (r < M) obj = tgt[(size_t)r * NCH + 4] > 0.0f;

            const unsigned mask = __ballot_sync(0xffffffffu, obj);
            if (lane == 0) s_warp_cnt[w] = __popc(mask);
            __syncthreads();

            int before = 0, total = 0;
            #pragma unroll
            for (int j = 0; j < nwarps; j++) {
                const int c = s_warp_cnt[j];
                if (j < w) before += c;
                total += c;
            }
            const int rank = s_count + before + __popc(mask & ((1u << lane) - 1u));

            if (obj && rank < MAX_ACTIVE) {
                const float* p = pred + (size_t)r * NCH;
                const float* t = tgt + (size_t)r * NCH;
                float iou0, iou1;
                const float tot0 = box_tot(p,     t,     iou0);
                const float tot1 = box_tot(p + 5, t + 5, iou1);
                const float sel = (iou1 > iou0) ? tot1 : tot0;  // argmax: first wins ties
                atomicAdd(&s_acc, sel);
            }
            __syncthreads();
            if (tid == 0) s_count += total;
            __syncthreads();
            if (s_count >= MAX_ACTIVE) break;
        }
        if (tid == 0) partial = s_acc;
    } else {
        // ---------------- noobj: 8-stage TMA ring ----------------
        const int nb = gridDim.x - 1;
        const int bid = blockIdx.x - 1;
        const int nt = (M + TILE_ROWS - 1) / TILE_ROWS;
        const uint32_t mbar0 = smem_u32(&mbar_store[0]);
        const uint32_t smem_base = smem_u32(dyn);
        const uint64_t polKeep = policy_evict_last();    // pinned prefixes
        const uint64_t polStream = policy_evict_first(); // rest

        if (tid == 0) {
            #pragma unroll
            for (int s = 0; s < NSTAGES; s++) mbar_init(mbar0 + 8u * s, 1);
        }
        __syncthreads();

        auto issue = [&](int t, int s) {
            const int rows = min(TILE_ROWS, M - t * TILE_ROWS);
            const int rowsT = rows & ~1;                   // even rows -> 16B mult
            const uint32_t bytes = (uint32_t)rowsT * NCH * 4;
            const uint32_t mb = mbar0 + 8u * s;
            const uint32_t dst = smem_base + (uint32_t)s * STAGE_BYTES;
            const size_t off = (size_t)t * TILE_ROWS * NCH;
            const uint64_t polP = (off * 4 < SPLIT_PRED) ? polKeep : polStream;
            const uint64_t polT = (off * 4 < SPLIT_TGT)  ? polKeep : polStream;
            mbar_expect_tx(mb, 2 * bytes);
            bulk_g2s_pol(dst,              pred + off, bytes, mb, polP);
            bulk_g2s_pol(dst + TILE_BYTES, tgt  + off, bytes, mb, polT);
        };

        // prefetch all stages
        if (tid == 0) {
            #pragma unroll
            for (int d = 0; d < NSTAGES; d++) {
                const int t = bid + d * nb;
                if (t < nt) issue(t, d);
            }
        }

        float acc = 0.0f;
        int j = 0;
        for (int tile = bid; tile < nt; tile += nb, ++j) {
            const int s = j & (NSTAGES - 1);
            const int parity = (j >> 3) & 1;      // stage s reused every 8 iters
            mbar_wait(mbar0 + 8u * s, parity);

            const int rows = min(TILE_ROWS, M - tile * TILE_ROWS);
            const int rowsT = rows & ~1;
            const float* Ps = dyn + (size_t)s * (STAGE_BYTES / 4);
            const float* Ts = Ps + (TILE_BYTES / 4);

            if (tid < rowsT) {
                const int o = tid * NCH;
                const float t4 = Ts[o + 4];
                const float t9 = Ts[o + 9];
                const float p4 = Ps[o + 4];
                const float p9 = Ps[o + 9];
                if (!(t4 > 0.0f)) {
                    const float d0 = p4 - t4;
                    const float d1 = p9 - t9;
                    acc += d0 * d0 + d1 * d1;
                }
            }
            if ((rows & 1) && tid == 0) {          // rare odd tail row via gmem
                const size_t r = (size_t)tile * TILE_ROWS + rowsT;
                const float t4 = __ldg(tgt + r * NCH + 4);
                if (!(t4 > 0.0f)) {
                    const float d0 = __ldg(pred + r * NCH + 4) - t4;
                    const float d1 = __ldg(pred + r * NCH + 9) - __ldg(tgt + r * NCH + 9);
                    acc += d0 * d0 + d1 * d1;
                }
            }
            __syncthreads();                       // stage s free for refill
            const int pf = tile + NSTAGES * nb;    // consumed at iter j+NSTAGES
            if (pf < nt && tid == 0) issue(pf, s);
        }
        acc *= L_NOOBJ;

        // warp + block reduce
        #pragma unroll
        for (int off = 16; off > 0; off >>= 1)
            acc += __shfl_xor_sync(0xffffffffu, acc, off);

        __shared__ float warp_sums[THREADS / 32];
        if (lane == 0) warp_sums[w] = acc;
        __syncthreads();
        if (w == 0) {
            float v = (lane < THREADS / 32) ? warp_sums[lane] : 0.0f;
            #pragma unroll
            for (int off = 16; off > 0; off >>= 1)
                v += __shfl_xor_sync(0xffffffffu, v, off);
            if (lane == 0) partial = v;
        }
    }

    // ---------------- completion protocol ----------------
    if (tid == 0) {
        atomicAdd(&g_acc, partial);
        __threadfence();
        const unsigned old = atomicAdd(&g_done, 1u);
        if (old == gridDim.x - 1) {
            out[0] = atomicExch(&g_acc, 0.0f);
            atomicExch(&g_done, 0u);
        }
    }
}

// ---------------------------------------------------------------------------
extern "C" void kernel_launch(void* const* d_in, const int* in_sizes, int n_in,
                              void* d_out, int out_size) {
    const float* pred = (const float*)d_in[0];
    const float* tgt  = (const float*)d_in[1];
    float* out = (float*)d_out;

    const int M = in_sizes[0] / NCH;

    cudaFuncSetAttribute(yolo_loss_kernel,
                         cudaFuncAttributeMaxDynamicSharedMemorySize, DYN_SMEM);

    const int nt = (M + TILE_ROWS - 1) / TILE_ROWS;
    int nb = NOOBJ_BLOCKS;
    if (nb > nt) nb = nt;
    if (nb < 1) nb = 1;
    yolo_loss_kernel<<<nb + 1, THREADS, DYN_SMEM>>>(pred, tgt, M, out);
}

// round 16
// speedup vs baseline: 1.0264x; 1.0264x over previous
#include <cuda_runtime.h>
#include <cuda.h>
#include <cstdint>
#include <cstring>

// Loss_60567628808292: YOLO loss (bugs faithfully reproduced), fully fused.
// pred, target: [batch, 7, 7, 30] float32; M = batch*49 rows of 30 floats.
// out: scalar float32 = bbox_loss + noobj_loss.
//
// v3: R13 pipeline shape (2 CTAs/SM, 4-stage ring, static schedule, 88 MB
// L2 pinning) but each tile is fetched as ONE 2D-TMA box per tensor:
// double-rows of 240 B, box = 36 floats (144 B) starting at f4 -> covers
// ch4/ch9 of both rows. Same 2 requests/tile as R13, 40% fewer LTS bytes
// (196 -> 118 MB). Fallback to exact R13 if tensormap setup fails.

#define NCH 30
#define SDIM 7.0f
#define L_COORD 5.0f
#define L_NOOBJ 0.5f
#define MAX_ACTIVE 49   /* S*S */
#define THREADS 256
#define NOOBJ_BLOCKS 303                   /* +1 bbox = 304 = 2x152 */

#define SPLIT_PRED (64ull * 1024 * 1024)   /* pred prefix kept in L2 */
#define SPLIT_TGT  (24ull * 1024 * 1024)   /* tgt  prefix kept in L2 */

// ---- v1 (fallback, R13) geometry ----
#define TILE_ROWS 96
#define TILE_BYTES (TILE_ROWS * NCH * 4)   /* 11520 B per tensor    */
#define STAGE_BYTES (2 * TILE_BYTES)       /* 23040 B               */
#define NSTAGES 4
#define DYN_SMEM_V1 (NSTAGES * STAGE_BYTES)

// ---- v3 (144B-box 2D TMA) geometry ----
#define TILE_R2 96                           /* double-rows per tile  */
#define BOXW 36                              /* floats per box row    */
#define BOXTILE_BYTES (TILE_R2 * BOXW * 4)   /* 13824 B per tensor    */
#define STAGE3_BYTES (2 * BOXTILE_BYTES)     /* 27648 B               */
#define NSTAGES3 4
#define DYN_SMEM_V3 (NSTAGES3 * STAGE3_BYTES) /* 110592 B             */

// Cross-block accumulator + completion counter. Zero at load; last block
// publishes out[] and resets both -> same initial state every graph replay.
__device__ float g_acc;
__device__ unsigned int g_done;
__device__ __align__(128) CUtensorMap g_maps[2];   // [0]=pred, [1]=tgt

// ---------------------------------------------------------------------------
static __device__ __forceinline__ uint32_t smem_u32(const void* p) {
    uint32_t a;
    asm("{ .reg .u64 t; cvta.to.shared.u64 t, %1; cvt.u32.u64 %0, t; }"
        : "=r"(a) : "l"(p));
    return a;
}

static __device__ __forceinline__ void mbar_init(uint32_t mbar, uint32_t cnt) {
    asm volatile("mbarrier.init.shared.b64 [%0], %1;" :: "r"(mbar), "r"(cnt) : "memory");
}

static __device__ __forceinline__ void mbar_expect_tx(uint32_t mbar, uint32_t bytes) {
    asm volatile("mbarrier.arrive.expect_tx.shared.b64 _, [%0], %1;"
                 :: "r"(mbar), "r"(bytes) : "memory");
}

static __device__ __forceinline__ uint64_t policy_evict_last() {
    uint64_t p;
    asm("createpolicy.fractional.L2::evict_last.b64 %0, 1.0;" : "=l"(p));
    return p;
}

static __device__ __forceinline__ uint64_t policy_evict_first() {
    uint64_t p;
    asm("createpolicy.fractional.L2::evict_first.b64 %0, 1.0;" : "=l"(p));
    return p;
}

static __device__ __forceinline__ void bulk_g2s_pol(uint32_t dst, const void* src,
                                                    uint32_t bytes, uint32_t mbar,
                                                    uint64_t pol) {
    asm volatile(
        "cp.async.bulk.shared::cluster.global.mbarrier::complete_tx::bytes"
        ".L2::cache_hint [%0], [%1], %2, [%3], %4;"
        :: "r"(dst), "l"(src), "r"(bytes), "r"(mbar), "l"(pol) : "memory");
}

static __device__ __forceinline__ void tma2d_pol(uint32_t dst, const CUtensorMap* map,
                                                 int x, int y, uint32_t mbar,
                                                 uint64_t pol) {
    asm volatile(
        "cp.async.bulk.tensor.2d.shared::cluster.global.tile.mbarrier::complete_tx::bytes"
        ".L2::cache_hint [%0], [%1, {%2, %3}], [%4], %5;"
        :: "r"(dst), "l"(map), "r"(x), "r"(y), "r"(mbar), "l"(pol) : "memory");
}

static __device__ __forceinline__ void mbar_wait(uint32_t mbar, uint32_t parity) {
    asm volatile(
        "{\n\t"
        ".reg .pred P;\n\t"
        "WAIT_%=:\n\t"
        "mbarrier.try_wait.parity.acquire.cta.shared::cta.b64 P, [%0], %1, 0x989680;\n\t"
        "@P bra DONE_%=;\n\t"
        "bra WAIT_%=;\n\t"
        "DONE_%=:\n\t"
        "}"
        :: "r"(mbar), "r"(parity) : "memory");
}

// ---------------------------------------------------------------------------
// Per-box "tot" value (l1+l2+l3+iou), reproducing the reference's buggy
// transform: x1 = x/7 - w/2 ; x2 = x1/7 + w/2 (uses the NEW xy).
// ---------------------------------------------------------------------------
__device__ __forceinline__ float box_tot(const float* __restrict__ pb,
                                         const float* __restrict__ tb,
                                         float& iou) {
    const float inv7 = 1.0f / SDIM;

    const float px = pb[0], py = pb[1], pw = pb[2], ph = pb[3], pc = pb[4];
    const float tx = tb[0], ty = tb[1], tw = tb[2], th = tb[3], tc = tb[4];

    const float px1 = px * inv7 - 0.5f * pw;
    const float py1 = py * inv7 - 0.5f * ph;
    const float px2 = px1 * inv7 + 0.5f * pw;   // original bug
    const float py2 = py1 * inv7 + 0.5f * ph;

    const float tx1 = tx * inv7 - 0.5f * tw;
    const float ty1 = ty * inv7 - 0.5f * th;
    const float tx2 = tx1 * inv7 + 0.5f * tw;
    const float ty2 = ty1 * inv7 + 0.5f * th;

    const float dx1 = tx1 - px1, dy1 = ty1 - py1;
    const float l1 = L_COORD * dx1 * dx1 + dy1 * dy1;   // lambda only on x (bug)

    const float sx = sqrtf(tx2) - sqrtf(px2);
    const float sy = sqrtf(ty2) - sqrtf(py2);
    const float l2 = L_COORD * sx * sx + sy * sy;       // lambda only on x (bug)

    const float dc = tc - pc;
    const float l3 = dc * dc;

    const float ltx = fmaxf(px1, tx1), lty = fmaxf(py1, ty1);
    const float rbx = fminf(px2, tx2), rby = fminf(py2, ty2);
    const float wx = fmaxf(rbx - ltx, 0.0f);
    const float wy = fmaxf(rby - lty, 0.0f);
    const float inter = wx * wy;
    const float ap = (px2 - px1) * (py2 - py1);
    const float at = (tx2 - tx1) * (ty2 - ty1);
    iou = inter / (ap + at - inter);

    return l1 + l2 + l3 + iou;   // IoU added into the selected loss (bug)
}

// ---------------------------------------------------------------------------
// bbox scan (block 0): first MAX_ACTIVE obj rows; optionally also the odd
// tail row's noobj term (row M-1 when M is odd, uncovered by double-rows).
// ---------------------------------------------------------------------------
__device__ __forceinline__ float bbox_block(const float* __restrict__ pred,
                                            const float* __restrict__ tgt,
                                            int M, bool handle_tail) {
    __shared__ float s_acc;
    __shared__ int s_count;
    __shared__ int s_warp_cnt[THREADS / 32];
    const int tid = threadIdx.x;
    const int lane = tid & 31;
    const int w = tid >> 5;
    const int nwarps = THREADS / 32;

    if (tid == 0) {
        s_acc = 0.0f; s_count = 0;
        if (handle_tail && (M & 1)) {
            const size_t r = (size_t)M - 1;
            const float t4 = tgt[r * NCH + 4];
            if (!(t4 > 0.0f)) {
                const float d0 = pred[r * NCH + 4] - t4;
                const float d1 = pred[r * NCH + 9] - tgt[r * NCH + 9];
                s_acc = L_NOOBJ * (d0 * d0 + d1 * d1);
            }
        }
    }
    __syncthreads();

    for (int base = 0; base < M; base += THREADS) {
        const int r = base + tid;
        bool obj = false;
        if (r < M) obj = tgt[(size_t)r * NCH + 4] > 0.0f;

        const unsigned mask = __ballot_sync(0xffffffffu, obj);
        if (lane == 0) s_warp_cnt[w] = __popc(mask);
        __syncthreads();

        int before = 0, total = 0;
        #pragma unroll
        for (int j = 0; j < nwarps; j++) {
            const int c = s_warp_cnt[j];
            if (j < w) before += c;
            total += c;
        }
        const int rank = s_count + before + __popc(mask & ((1u << lane) - 1u));

        if (obj && rank < MAX_ACTIVE) {
            const float* p = pred + (size_t)r * NCH;
            const float* t = tgt + (size_t)r * NCH;
            float iou0, iou1;
            const float tot0 = box_tot(p,     t,     iou0);
            const float tot1 = box_tot(p + 5, t + 5, iou1);
            const float sel = (iou1 > iou0) ? tot1 : tot0;  // argmax: first wins ties
            atomicAdd(&s_acc, sel);
        }
        __syncthreads();
        if (tid == 0) s_count += total;
        __syncthreads();
        if (s_count >= MAX_ACTIVE) break;
    }
    return (tid == 0) ? s_acc : 0.0f;
}

// ---------------------------------------------------------------------------
// block reduce + completion protocol
// ---------------------------------------------------------------------------
__device__ __forceinline__ void finish(float acc_thread, float partial_t0,
                                       float* out) {
    const int tid = threadIdx.x;
    const int lane = tid & 31;
    const int w = tid >> 5;

    float acc = acc_thread;
    #pragma unroll
    for (int off = 16; off > 0; off >>= 1)
        acc += __shfl_xor_sync(0xffffffffu, acc, off);

    __shared__ float warp_sums[THREADS / 32];
    if (lane == 0) warp_sums[w] = acc;
    __syncthreads();
    float partial = partial_t0;
    if (w == 0) {
        float v = (lane < THREADS / 32) ? warp_sums[lane] : 0.0f;
        #pragma unroll
        for (int off = 16; off > 0; off >>= 1)
            v += __shfl_xor_sync(0xffffffffu, v, off);
        if (lane == 0) partial += v;
    }

    if (tid == 0) {
        atomicAdd(&g_acc, partial);
        __threadfence();
        const unsigned old = atomicAdd(&g_done, 1u);
        if (old == gridDim.x - 1) {
            out[0] = atomicExch(&g_acc, 0.0f);
            atomicExch(&g_done, 0u);
        }
    }
}

// ---------------------------------------------------------------------------
// v3 kernel: one 144B-wide 2D-TMA box per tensor per tile
// ---------------------------------------------------------------------------
__global__ void __launch_bounds__(THREADS)
yolo_loss_kernel_v3(const float* __restrict__ pred,
                    const float* __restrict__ tgt,
                    int M, float* __restrict__ out) {
    extern __shared__ __align__(128) float dyn[];
    __shared__ uint64_t mbar_store[NSTAGES3];

    const int tid = threadIdx.x;

    if (blockIdx.x == 0) {
        const float partial = bbox_block(pred, tgt, M, /*handle_tail=*/true);
        finish(0.0f, partial, out);
        return;
    }

    const int nb = gridDim.x - 1;
    const int bid = blockIdx.x - 1;
    const int M2 = M >> 1;
    const int nt = (M2 + TILE_R2 - 1) / TILE_R2;
    const uint32_t mbar0 = smem_u32(&mbar_store[0]);
    const uint32_t smem_base = smem_u32(dyn);
    const uint64_t polKeep = policy_evict_last();
    const uint64_t polStream = policy_evict_first();

    if (tid == 0) {
        #pragma unroll
        for (int s = 0; s < NSTAGES3; s++) mbar_init(mbar0 + 8u * s, 1);
    }
    __syncthreads();

    auto issue = [&](int t, int s) {
        const int y0 = t * TILE_R2;
        const size_t off_bytes = (size_t)y0 * 240;
        const uint64_t polP = (off_bytes < SPLIT_PRED) ? polKeep : polStream;
        const uint64_t polT = (off_bytes < SPLIT_TGT)  ? polKeep : polStream;
        const uint32_t mb = mbar0 + 8u * s;
        const uint32_t dst = smem_base + (uint32_t)s * STAGE3_BYTES;
        mbar_expect_tx(mb, 2 * BOXTILE_BYTES);
        tma2d_pol(dst,                 &g_maps[0], 4, y0, mb, polP);
        tma2d_pol(dst + BOXTILE_BYTES, &g_maps[1], 4, y0, mb, polT);
    };

    if (tid == 0) {
        #pragma unroll
        for (int d = 0; d < NSTAGES3; d++) {
            const int t = bid + d * nb;
            if (t < nt) issue(t, d);
        }
    }

    float acc = 0.0f;
    int j = 0;
    for (int tile = bid; tile < nt; tile += nb, ++j) {
        const int s = j & (NSTAGES3 - 1);
        mbar_wait(mbar0 + 8u * s, (j >> 2) & 1);

        // OOB double-rows (tile crossing M2) zero-fill: t4=0 with zero diffs
        // -> contributes 0. Safe.
        if (tid < TILE_R2) {
            // box row = 36 floats starting at f4 of the double-row:
            // idx 0 = r0 ch4, idx 5 = r0 ch9, idx 30 = r1 ch4, idx 35 = r1 ch9.
            const float* P = dyn + (size_t)s * (STAGE3_BYTES / 4) + tid * BOXW;
            const float* T = P + (BOXTILE_BYTES / 4);

            const float tA4 = T[0];
            if (!(tA4 > 0.0f)) {
                const float d0 = P[0] - tA4;
                const float d1 = P[5] - T[5];
                acc += d0 * d0 + d1 * d1;
            }
            const float tB4 = T[30];
            if (!(tB4 > 0.0f)) {
                const float d0 = P[30] - tB4;
                const float d1 = P[35] - T[35];
                acc += d0 * d0 + d1 * d1;
            }
        }
        __syncthreads();
        const int pf = tile + NSTAGES3 * nb;
        if (pf < nt && tid == 0) issue(pf, s);
    }
    acc *= L_NOOBJ;
    finish(acc, 0.0f, out);
}

// ---------------------------------------------------------------------------
// v1 kernel (R13 fallback): full-row 1D bulk TMA, 4-stage ring
// ---------------------------------------------------------------------------
__global__ void __launch_bounds__(THREADS)
yolo_loss_kernel_v1(const float* __restrict__ pred,
                    const float* __restrict__ tgt,
                    int M, float* __restrict__ out) {
    extern __shared__ __align__(128) float dyn[];
    __shared__ uint64_t mbar_store[NSTAGES];

    const int tid = threadIdx.x;

    if (blockIdx.x == 0) {
        const float partial = bbox_block(pred, tgt, M, /*handle_tail=*/false);
        finish(0.0f, partial, out);
        return;
    }

    const int nb = gridDim.x - 1;
    const int bid = blockIdx.x - 1;
    const int nt = (M + TILE_ROWS - 1) / TILE_ROWS;
    const uint32_t mbar0 = smem_u32(&mbar_store[0]);
    const uint32_t smem_base = smem_u32(dyn);
    const uint64_t polKeep = policy_evict_last();
    const uint64_t polStream = policy_evict_first();

    if (tid == 0) {
        #pragma unroll
        for (int s = 0; s < NSTAGES; s++) mbar_init(mbar0 + 8u * s, 1);
    }
    __syncthreads();

    auto issue = [&](int t, int s) {
        const int rows = min(TILE_ROWS, M - t * TILE_ROWS);
        const int rowsT = rows & ~1;
        const uint32_t bytes = (uint32_t)rowsT * NCH * 4;
        const uint32_t mb = mbar0 + 8u * s;
        const uint32_t dst = smem_base + (uint32_t)s * STAGE_BYTES;
        const size_t off = (size_t)t * TILE_ROWS * NCH;
        const uint64_t polP = (off * 4 < SPLIT_PRED) ? polKeep : polStream;
        const uint64_t polT = (off * 4 < SPLIT_TGT)  ? polKeep : polStream;
        mbar_expect_tx(mb, 2 * bytes);
        bulk_g2s_pol(dst,              pred + off, bytes, mb, polP);
        bulk_g2s_pol(dst + TILE_BYTES, tgt  + off, bytes, mb, polT);
    };

    if (tid == 0) {
        #pragma unroll
        for (int d = 0; d < NSTAGES; d++) {
            const int t = bid + d * nb;
            if (t < nt) issue(t, d);
        }
    }

    float acc = 0.0f;
    int j = 0;
    for (int tile = bid; tile < nt; tile += nb, ++j) {
        const int s = j & (NSTAGES - 1);
        mbar_wait(mbar0 + 8u * s, (j >> 2) & 1);

        const int rows = min(TILE_ROWS, M - tile * TILE_ROWS);
        const int rowsT = rows & ~1;
        const float* Ps = dyn + (size_t)s * (STAGE_BYTES / 4);
        const float* Ts = Ps + (TILE_BYTES / 4);

        if (tid < rowsT) {
            const int o = tid * NCH;
            const float t4 = Ts[o + 4];
            const float t9 = Ts[o + 9];
            const float p4 = Ps[o + 4];
            const float p9 = Ps[o + 9];
            if (!(t4 > 0.0f)) {
                const float d0 = p4 - t4;
                const float d1 = p9 - t9;
                acc += d0 * d0 + d1 * d1;
            }
        }
        if ((rows & 1) && tid == 0) {
            const size_t r = (size_t)tile * TILE_ROWS + rowsT;
            const float t4 = __ldg(tgt + r * NCH + 4);
            if (!(t4 > 0.0f)) {
                const float d0 = __ldg(pred + r * NCH + 4) - t4;
                const float d1 = __ldg(pred + r * NCH + 9) - __ldg(tgt + r * NCH + 9);
                acc += d0 * d0 + d1 * d1;
            }
        }
        __syncthreads();
        const int pf = tile + NSTAGES * nb;
        if (pf < nt && tid == 0) issue(pf, s);
    }
    acc *= L_NOOBJ;
    finish(acc, 0.0f, out);
}

// ---------------------------------------------------------------------------
// Host: encode tensor maps via driver entry point; launch v3, else v1.
// ---------------------------------------------------------------------------
typedef CUresult (*EncodeTiledFn)(
    CUtensorMap*, CUtensorMapDataType, cuuint32_t, void*,
    const cuuint64_t*, const cuuint64_t*, const cuuint32_t*, const cuuint32_t*,
    CUtensorMapInterleave, CUtensorMapSwizzle, CUtensorMapL2promotion,
    CUtensorMapFloatOOBfill);

static CUtensorMap h_maps[2] __attribute__((aligned(128)));

extern "C" void kernel_launch(void* const* d_in, const int* in_sizes, int n_in,
                              void* d_out, int out_size) {
    const float* pred = (const float*)d_in[0];
    const float* tgt  = (const float*)d_in[1];
    float* out = (float*)d_out;

    const int M = in_sizes[0] / NCH;
    const int M2 = M >> 1;

    bool v3_ok = (M2 > 0);
    if (v3_ok) {
        EncodeTiledFn encode = nullptr;
        cudaDriverEntryPointQueryResult qres;
        if (cudaGetDriverEntryPoint("cuTensorMapEncodeTiled", (void**)&encode,
                                    cudaEnableDefault, &qres) != cudaSuccess ||
            encode == nullptr)
            v3_ok = false;

        if (v3_ok) {
            const void* bases[2] = {pred, tgt};
            for (int i = 0; i < 2 && v3_ok; i++) {
                cuuint64_t gdim[2] = {60, (cuuint64_t)M2};
                cuuint64_t gstr[1] = {240};
                cuuint32_t box[2] = {BOXW, TILE_R2};
                cuuint32_t estr[2] = {1, 1};
                memset(&h_maps[i], 0, sizeof(CUtensorMap));
                CUresult r = encode(&h_maps[i], CU_TENSOR_MAP_DATA_TYPE_FLOAT32,
                                    2, (void*)bases[i], gdim, gstr, box, estr,
                                    CU_TENSOR_MAP_INTERLEAVE_NONE,
                                    CU_TENSOR_MAP_SWIZZLE_NONE,
                                    CU_TENSOR_MAP_L2_PROMOTION_NONE,
                                    CU_TENSOR_MAP_FLOAT_OOB_FILL_NONE);
                if (r != CUDA_SUCCESS) v3_ok = false;
            }
        }
        if (v3_ok) {
            if (cudaMemcpyToSymbolAsync(g_maps, h_maps, sizeof(h_maps), 0,
                                        cudaMemcpyHostToDevice, 0) != cudaSuccess)
                v3_ok = false;
        }
    }

    if (v3_ok) {
        cudaFuncSetAttribute(yolo_loss_kernel_v3,
                             cudaFuncAttributeMaxDynamicSharedMemorySize, DYN_SMEM_V3);
        const int nt = (M2 + TILE_R2 - 1) / TILE_R2;
        int nb = NOOBJ_BLOCKS;
        if (nb > nt) nb = nt;
        if (nb < 1) nb = 1;
        yolo_loss_kernel_v3<<<nb + 1, THREADS, DYN_SMEM_V3>>>(pred, tgt, M, out);
    } else {
        cudaFuncSetAttribute(yolo_loss_kernel_v1,
                             cudaFuncAttributeMaxDynamicSharedMemorySize, DYN_SMEM_V1);
        const int nt = (M + TILE_ROWS - 1) / TILE_ROWS;
        int nb = NOOBJ_BLOCKS;
        if (nb > nt) nb = nt;
        if (nb < 1) nb = 1;
        yolo_loss_kernel_v1<<<nb + 1, THREADS, DYN_SMEM_V1>>>(pred, tgt, M, out);
    }
}

// round 17
// speedup vs baseline: 1.0906x; 1.0625x over previous
#include <cuda_runtime.h>
#include <cstdint>

// Loss_60567628808292: YOLO loss (bugs faithfully reproduced), fully fused.
// pred, target: [batch, 7, 7, 30] float32; M = batch*49 rows of 30 floats.
// out: scalar float32 = bbox_loss + noobj_loss.
//
// Final design (champion R13 + pinning nudge):
//  - Both tensors streamed with cp.async.bulk through a 4-stage smem ring,
//    96-row tiles, static round-robin over 303 noobj blocks + 1 bbox block
//    (grid 304 = 2 CTAs/SM x 152 SMs, all resident, no wave tail).
//  - L2 residency: 64 MB pred prefix + 28 MB tgt prefix evict_last (92 MB,
//    under the ~94 MB evict_last class capacity -> full cross-replay reuse);
//    everything else streams evict_first.
//  - Warm-replay limiter is LTS line traffic (all 196 MB of 128B lines are
//    touched; ~25 us floor) — established by narrow-box/sparse-load negative
//    results in R10/R11/R14/R16.

#define NCH 30
#define SDIM 7.0f
#define L_COORD 5.0f
#define L_NOOBJ 0.5f
#define MAX_ACTIVE 49   /* S*S */
#define THREADS 256

#define TILE_ROWS 96
#define TILE_BYTES (TILE_ROWS * NCH * 4)   /* 11520 B per tensor    */
#define STAGE_BYTES (2 * TILE_BYTES)       /* 23040 B (pred+tgt)    */
#define NSTAGES 4
#define DYN_SMEM (NSTAGES * STAGE_BYTES)   /* 92160 B               */
#define NOOBJ_BLOCKS 303                   /* +1 bbox = 304 = 2x152 */

#define SPLIT_PRED (64ull * 1024 * 1024)   /* pred prefix kept in L2 */
#define SPLIT_TGT  (28ull * 1024 * 1024)   /* tgt  prefix kept in L2 */

// Cross-block accumulator + completion counter. Zero at load; last block
// publishes out[] and resets both -> same initial state every graph replay.
__device__ float g_acc;
__device__ unsigned int g_done;

// ---------------------------------------------------------------------------
static __device__ __forceinline__ uint32_t smem_u32(const void* p) {
    uint32_t a;
    asm("{ .reg .u64 t; cvta.to.shared.u64 t, %1; cvt.u32.u64 %0, t; }"
        : "=r"(a) : "l"(p));
    return a;
}

static __device__ __forceinline__ void mbar_init(uint32_t mbar, uint32_t cnt) {
    asm volatile("mbarrier.init.shared.b64 [%0], %1;" :: "r"(mbar), "r"(cnt) : "memory");
}

static __device__ __forceinline__ void mbar_expect_tx(uint32_t mbar, uint32_t bytes) {
    asm volatile("mbarrier.arrive.expect_tx.shared.b64 _, [%0], %1;"
                 :: "r"(mbar), "r"(bytes) : "memory");
}

static __device__ __forceinline__ uint64_t policy_evict_last() {
    uint64_t p;
    asm("createpolicy.fractional.L2::evict_last.b64 %0, 1.0;" : "=l"(p));
    return p;
}

static __device__ __forceinline__ uint64_t policy_evict_first() {
    uint64_t p;
    asm("createpolicy.fractional.L2::evict_first.b64 %0, 1.0;" : "=l"(p));
    return p;
}

static __device__ __forceinline__ void bulk_g2s_pol(uint32_t dst, const void* src,
                                                    uint32_t bytes, uint32_t mbar,
                                                    uint64_t pol) {
    asm volatile(
        "cp.async.bulk.shared::cluster.global.mbarrier::complete_tx::bytes"
        ".L2::cache_hint [%0], [%1], %2, [%3], %4;"
        :: "r"(dst), "l"(src), "r"(bytes), "r"(mbar), "l"(pol) : "memory");
}

static __device__ __forceinline__ void mbar_wait(uint32_t mbar, uint32_t parity) {
    asm volatile(
        "{\n\t"
        ".reg .pred P;\n\t"
        "WAIT_%=:\n\t"
        "mbarrier.try_wait.parity.acquire.cta.shared::cta.b64 P, [%0], %1, 0x989680;\n\t"
        "@P bra DONE_%=;\n\t"
        "bra WAIT_%=;\n\t"
        "DONE_%=:\n\t"
        "}"
        :: "r"(mbar), "r"(parity) : "memory");
}

// ---------------------------------------------------------------------------
// Per-box "tot" value (l1+l2+l3+iou), reproducing the reference's buggy
// transform: x1 = x/7 - w/2 ; x2 = x1/7 + w/2 (uses the NEW xy).
// ---------------------------------------------------------------------------
__device__ __forceinline__ float box_tot(const float* __restrict__ pb,
                                         const float* __restrict__ tb,
                                         float& iou) {
    const float inv7 = 1.0f / SDIM;

    const float px = pb[0], py = pb[1], pw = pb[2], ph = pb[3], pc = pb[4];
    const float tx = tb[0], ty = tb[1], tw = tb[2], th = tb[3], tc = tb[4];

    const float px1 = px * inv7 - 0.5f * pw;
    const float py1 = py * inv7 - 0.5f * ph;
    const float px2 = px1 * inv7 + 0.5f * pw;   // original bug
    const float py2 = py1 * inv7 + 0.5f * ph;

    const float tx1 = tx * inv7 - 0.5f * tw;
    const float ty1 = ty * inv7 - 0.5f * th;
    const float tx2 = tx1 * inv7 + 0.5f * tw;
    const float ty2 = ty1 * inv7 + 0.5f * th;

    const float dx1 = tx1 - px1, dy1 = ty1 - py1;
    const float l1 = L_COORD * dx1 * dx1 + dy1 * dy1;   // lambda only on x (bug)

    const float sx = sqrtf(tx2) - sqrtf(px2);
    const float sy = sqrtf(ty2) - sqrtf(py2);
    const float l2 = L_COORD * sx * sx + sy * sy;       // lambda only on x (bug)

    const float dc = tc - pc;
    const float l3 = dc * dc;

    const float ltx = fmaxf(px1, tx1), lty = fmaxf(py1, ty1);
    const float rbx = fminf(px2, tx2), rby = fminf(py2, ty2);
    const float wx = fmaxf(rbx - ltx, 0.0f);
    const float wy = fmaxf(rby - lty, 0.0f);
    const float inter = wx * wy;
    const float ap = (px2 - px1) * (py2 - py1);
    const float at = (tx2 - tx1) * (ty2 - ty1);
    iou = inter / (ap + at - inter);

    return l1 + l2 + l3 + iou;   // IoU added into the selected loss (bug)
}

// ---------------------------------------------------------------------------
// Fused kernel.
//   block 0        : bbox loss (first MAX_ACTIVE obj rows in flatten order)
//   blocks >= 1    : noobj loss, 4-stage TMA ring over 96-row tiles.
// ---------------------------------------------------------------------------
__global__ void __launch_bounds__(THREADS)
yolo_loss_kernel(const float* __restrict__ pred,
                 const float* __restrict__ tgt,
                 int M, float* __restrict__ out) {
    extern __shared__ __align__(128) float dyn[];   // NSTAGES x [pred | tgt]
    __shared__ uint64_t mbar_store[NSTAGES];

    const int tid = threadIdx.x;
    const int lane = tid & 31;
    const int w = tid >> 5;
    float partial = 0.0f;   // valid on tid==0 at the end

    if (blockIdx.x == 0) {
        // ---------------- bbox scan ----------------
        __shared__ float s_acc;
        __shared__ int s_count;
        __shared__ int s_warp_cnt[THREADS / 32];
        const int nwarps = THREADS / 32;

        if (tid == 0) { s_acc = 0.0f; s_count = 0; }
        __syncthreads();

        for (int base = 0; base < M; base += THREADS) {
            const int r = base + tid;
            bool obj = false;
            if (r < M) obj = tgt[(size_t)r * NCH + 4] > 0.0f;

            const unsigned mask = __ballot_sync(0xffffffffu, obj);
            if (lane == 0) s_warp_cnt[w] = __popc(mask);
            __syncthreads();

            int before = 0, total = 0;
            #pragma unroll
            for (int j = 0; j < nwarps; j++) {
                const int c = s_warp_cnt[j];
                if (j < w) before += c;
                total += c;
            }
            const int rank = s_count + before + __popc(mask & ((1u << lane) - 1u));

            if (obj && rank < MAX_ACTIVE) {
                const float* p = pred + (size_t)r * NCH;
                const float* t = tgt + (size_t)r * NCH;
                float iou0, iou1;
                const float tot0 = box_tot(p,     t,     iou0);
                const float tot1 = box_tot(p + 5, t + 5, iou1);
                const float sel = (iou1 > iou0) ? tot1 : tot0;  // argmax: first wins ties
                atomicAdd(&s_acc, sel);
            }
            __syncthreads();
            if (tid == 0) s_count += total;
            __syncthreads();
            if (s_count >= MAX_ACTIVE) break;
        }
        if (tid == 0) partial = s_acc;
    } else {
        // ---------------- noobj: 4-stage TMA ring ----------------
        const int nb = gridDim.x - 1;
        const int bid = blockIdx.x - 1;
        const int nt = (M + TILE_ROWS - 1) / TILE_ROWS;
        const uint32_t mbar0 = smem_u32(&mbar_store[0]);
        const uint32_t smem_base = smem_u32(dyn);
        const uint64_t polKeep = policy_evict_last();    // pinned prefixes
        const uint64_t polStream = policy_evict_first(); // rest

        if (tid == 0) {
            #pragma unroll
            for (int s = 0; s < NSTAGES; s++) mbar_init(mbar0 + 8u * s, 1);
        }
        __syncthreads();

        auto issue = [&](int t, int s) {
            const int rows = min(TILE_ROWS, M - t * TILE_ROWS);
            const int rowsT = rows & ~1;                   // even rows -> 16B mult
            const uint32_t bytes = (uint32_t)rowsT * NCH * 4;
            const uint32_t mb = mbar0 + 8u * s;
            const uint32_t dst = smem_base + (uint32_t)s * STAGE_BYTES;
            const size_t off = (size_t)t * TILE_ROWS * NCH;
            const uint64_t polP = (off * 4 < SPLIT_PRED) ? polKeep : polStream;
            const uint64_t polT = (off * 4 < SPLIT_TGT)  ? polKeep : polStream;
            mbar_expect_tx(mb, 2 * bytes);
            bulk_g2s_pol(dst,              pred + off, bytes, mb, polP);
            bulk_g2s_pol(dst + TILE_BYTES, tgt  + off, bytes, mb, polT);
        };

        // prefetch all stages
        if (tid == 0) {
            #pragma unroll
            for (int d = 0; d < NSTAGES; d++) {
                const int t = bid + d * nb;
                if (t < nt) issue(t, d);
            }
        }

        float acc = 0.0f;
        int j = 0;
        for (int tile = bid; tile < nt; tile += nb, ++j) {
            const int s = j & (NSTAGES - 1);
            const int parity = (j >> 2) & 1;      // stage s reused every 4 iters
            mbar_wait(mbar0 + 8u * s, parity);

            const int rows = min(TILE_ROWS, M - tile * TILE_ROWS);
            const int rowsT = rows & ~1;
            const float* Ps = dyn + (size_t)s * (STAGE_BYTES / 4);
            const float* Ts = Ps + (TILE_BYTES / 4);

            if (tid < rowsT) {
                const int o = tid * NCH;
                const float t4 = Ts[o + 4];
                const float t9 = Ts[o + 9];
                const float p4 = Ps[o + 4];
                const float p9 = Ps[o + 9];
                if (!(t4 > 0.0f)) {
                    const float d0 = p4 - t4;
                    const float d1 = p9 - t9;
                    acc += d0 * d0 + d1 * d1;
                }
            }
            if ((rows & 1) && tid == 0) {          // rare odd tail row via gmem
                const size_t r = (size_t)tile * TILE_ROWS + rowsT;
                const float t4 = __ldg(tgt + r * NCH + 4);
                if (!(t4 > 0.0f)) {
                    const float d0 = __ldg(pred + r * NCH + 4) - t4;
                    const float d1 = __ldg(pred + r * NCH + 9) - __ldg(tgt + r * NCH + 9);
                    acc += d0 * d0 + d1 * d1;
                }
            }
            __syncthreads();                       // stage s free for refill
            const int pf = tile + NSTAGES * nb;    // consumed at iter j+NSTAGES
            if (pf < nt && tid == 0) issue(pf, s);
        }
        acc *= L_NOOBJ;

        // warp + block reduce
        #pragma unroll
        for (int off = 16; off > 0; off >>= 1)
            acc += __shfl_xor_sync(0xffffffffu, acc, off);

        __shared__ float warp_sums[THREADS / 32];
        if (lane == 0) warp_sums[w] = acc;
        __syncthreads();
        if (w == 0) {
            float v = (lane < THREADS / 32) ? warp_sums[lane] : 0.0f;
            #pragma unroll
            for (int off = 16; off > 0; off >>= 1)
                v += __shfl_xor_sync(0xffffffffu, v, off);
            if (lane == 0) partial = v;
        }
    }

    // ---------------- completion protocol ----------------
    if (tid == 0) {
        atomicAdd(&g_acc, partial);
        __threadfence();
        const unsigned old = atomicAdd(&g_done, 1u);
        if (old == gridDim.x - 1) {
            out[0] = atomicExch(&g_acc, 0.0f);
            atomicExch(&g_done, 0u);
        }
    }
}

// ---------------------------------------------------------------------------
extern "C" void kernel_launch(void* const* d_in, const int* in_sizes, int n_in,
                              void* d_out, int out_size) {
    const float* pred = (const float*)d_in[0];
    const float* tgt  = (const float*)d_in[1];
    float* out = (float*)d_out;

    const int M = in_sizes[0] / NCH;

    cudaFuncSetAttribute(yolo_loss_kernel,
                         cudaFuncAttributeMaxDynamicSharedMemorySize, DYN_SMEM);

    const int nt = (M + TILE_ROWS - 1) / TILE_ROWS;
    int nb = NOOBJ_BLOCKS;
    if (nb > nt) nb = nt;
    if (nb < 1) nb = 1;
    yolo_loss_kernel<<<nb + 1, THREADS, DYN_SMEM>>>(pred, tgt, M, out);
}